// round 2
// baseline (speedup 1.0000x reference)
#include <cuda_runtime.h>
#include <cuda_fp16.h>

// B=4, C=64, D=16, H=64, W=64, C8=8, topk k=38 -> threshold = sorted_asc[26]
#define EPSBN 1e-5f
typedef unsigned long long ull;

// ---- smem layout (floats) ----
// xs: 64 channels x 12 rows (h-2..h+9) x pitch 72 (col = w+2, zeros at 0,1,66..71)
#define CH_STRIDE 864            // 12*72
#define XS_FLOATS 55296          // 64*864
#define W1T_OFF   55296          // 512: w1t[c*8+o], bn2-scale folded
#define W2_OFF    55808          // 512: w2[c*8+o]
#define B1_OFF    56320          // 8
#define B2C_OFF   56328          // 64
#define ALPHA_OFF 56392          // 1
#define SMEM_FLOATS 56393
#define SMEM_BYTES (SMEM_FLOATS * 4)   // 225572 <= 227KB

__device__ __forceinline__ float silu_f(float v) {
  return v * (1.0f / (1.0f + __expf(-v)));
}
__device__ __forceinline__ ull pk(float lo, float hi) {
  ull r; asm("mov.b64 %0,{%1,%2};" : "=l"(r) : "f"(lo), "f"(hi)); return r;
}
__device__ __forceinline__ void upk(float& lo, float& hi, ull v) {
  asm("mov.b64 {%0,%1},%2;" : "=f"(lo), "=f"(hi) : "l"(v));
}
__device__ __forceinline__ ull fma2(ull a, ull b, ull c) {
  ull d; asm("fma.rn.f32x2 %0,%1,%2,%3;" : "=l"(d) : "l"(a), "l"(b), "l"(c)); return d;
}

// y1 fp16 storage in dead halo rows of a channel:
// half2 slot k (= h*32 + w/2, k in 0..255) -> float index off(k) inside channel
__device__ __forceinline__ int y1off(int k) { return (k < 144) ? k : k + 576; }

// fully unrolled 64-element bitonic sort (registers only)
__device__ __forceinline__ void sort64(float* s) {
  #pragma unroll
  for (int k = 2; k <= 64; k <<= 1) {
    #pragma unroll
    for (int j = k >> 1; j > 0; j >>= 1) {
      #pragma unroll
      for (int i = 0; i < 64; i++) {
        int l = i ^ j;
        if (l > i) {
          float a = s[i], b = s[l];
          float lo = fminf(a, b), hi = fmaxf(a, b);
          if ((i & k) == 0) { s[i] = lo; s[l] = hi; }
          else              { s[i] = hi; s[l] = lo; }
        }
      }
    }
  }
}

// attn value for channel c at this thread's location (bit-identical both calls)
__device__ __forceinline__ float attn_val(const float* __restrict__ sm, int c,
                                          int yoff, int wpar, const ull* hb2) {
  ull acc = pk(sm[B2C_OFF + c], 0.0f);
  float4 wa = *reinterpret_cast<const float4*>(&sm[W2_OFF + c * 8]);
  float4 wb = *reinterpret_cast<const float4*>(&sm[W2_OFF + c * 8 + 4]);
  acc = fma2(pk(wa.x, wa.y), hb2[0], acc);
  acc = fma2(pk(wa.z, wa.w), hb2[1], acc);
  acc = fma2(pk(wb.x, wb.y), hb2[2], acc);
  acc = fma2(pk(wb.z, wb.w), hb2[3], acc);
  float lo, hi; upk(lo, hi, acc);
  float y2 = lo + hi;
  unsigned ub = *reinterpret_cast<const unsigned*>(&sm[c * CH_STRIDE + yoff]);
  __half2 hh = *reinterpret_cast<__half2*>(&ub);
  float2 f = __half22float2(hh);
  float y1v = wpar ? f.y : f.x;
  return y1v * y2;
}

__global__ void __launch_bounds__(512)
k_fused(const float* __restrict__ x, float* __restrict__ out,
        const float* __restrict__ wdw,
        const float* __restrict__ g1, const float* __restrict__ be1,
        const float* __restrict__ m1, const float* __restrict__ v1,
        const float* __restrict__ wp1, const float* __restrict__ bp1,
        const float* __restrict__ g2, const float* __restrict__ be2,
        const float* __restrict__ m2, const float* __restrict__ v2,
        const float* __restrict__ wp2, const float* __restrict__ bp2,
        const float* __restrict__ alpha) {
  extern __shared__ float sm[];
  int tid = threadIdx.x;
  int bx = blockIdx.x;
  int b = bx >> 7, d = (bx >> 3) & 15, hs = bx & 7;

  // ---- phase 0: zero x slab (halo + edge cols) ----
  #pragma unroll 4
  for (int i = tid; i < XS_FLOATS; i += 512) sm[i] = 0.0f;
  __syncthreads();

  // ---- phase 1: params fold + x slab load ----
  {
    int o = tid & 7, c = tid >> 3;
    float s2 = __ldg(g2 + o) * rsqrtf(__ldg(v2 + o) + EPSBN);
    sm[W1T_OFF + c * 8 + o] = __ldg(wp1 + o * 64 + c) * s2;
    sm[W2_OFF + c * 8 + o]  = __ldg(wp2 + c * 8 + o);
    if (tid < 8)  sm[B1_OFF + tid] = (__ldg(bp1 + tid) - __ldg(m2 + tid)) * s2 + __ldg(be2 + tid);
    if (tid < 64) sm[B2C_OFF + tid] = __ldg(bp2 + tid);
    if (tid == 0) sm[ALPHA_OFF] = __ldg(alpha);
  }
  const float* xb = x + (size_t)b * 4194304 + (size_t)d * 4096;
  #pragma unroll
  for (int it = 0; it < 24; it++) {
    int i = tid + it * 512;              // 12288 float4 tiles
    int r = i >> 10, rem = i & 1023, c = rem >> 4, q = rem & 15;
    int h = hs * 8 + r - 2;
    if ((unsigned)h < 64u) {
      float4 v = *reinterpret_cast<const float4*>(xb + (size_t)c * 65536 + h * 64 + q * 4);
      float* dst = &sm[c * CH_STRIDE + r * 72 + q * 4 + 2];
      dst[0] = v.x; dst[1] = v.y; dst[2] = v.z; dst[3] = v.w;
    }
  }
  __syncthreads();

  // ---- phase 2: depthwise 5x5 conv + BN + SiLU -> fp16 y1 in dead halo rows ----
  {
    int cc = tid >> 3, sub = tid & 7;
    float s1 = __ldg(g1 + cc) * rsqrtf(__ldg(v1 + cc) + EPSBN);
    float t1 = __ldg(be1 + cc) - __ldg(m1 + cc) * s1;
    ull W2r[25];
    #pragma unroll
    for (int j = 0; j < 25; j++) {
      float w = __ldg(wdw + cc * 25 + j) * s1;
      W2r[j] = pk(w, w);
    }
    const float* chan = &sm[cc * CH_STRIDE];

    // group g = 8*i + sub -> h = g>>4 (0..7), wq = g&15; outputs w = 4wq..4wq+3
    // pass A: h in {0,1,6,7} (these READ halo rows) -> buffer in regs
    const int iA[8] = {0, 1, 2, 3, 12, 13, 14, 15};
    unsigned youtA[16];
    #pragma unroll
    for (int ii = 0; ii < 8; ii++) {
      int g = 8 * iA[ii] + sub;
      int h = g >> 4, wq = g & 15;
      ull A01 = pk(t1, t1), A23 = A01;
      #pragma unroll
      for (int r = 0; r < 5; r++) {
        const float* row = chan + (h + r) * 72 + wq * 4;
        float4 va = *reinterpret_cast<const float4*>(row);
        float4 vb = *reinterpret_cast<const float4*>(row + 4);
        ull P01 = pk(va.x, va.y), P12 = pk(va.y, va.z), P23 = pk(va.z, va.w),
            P34 = pk(va.w, vb.x), P45 = pk(vb.x, vb.y), P56 = pk(vb.y, vb.z),
            P67 = pk(vb.z, vb.w);
        const ull* Wr = &W2r[r * 5];
        A01 = fma2(Wr[0], P01, A01); A01 = fma2(Wr[1], P12, A01);
        A01 = fma2(Wr[2], P23, A01); A01 = fma2(Wr[3], P34, A01);
        A01 = fma2(Wr[4], P45, A01);
        A23 = fma2(Wr[0], P23, A23); A23 = fma2(Wr[1], P34, A23);
        A23 = fma2(Wr[2], P45, A23); A23 = fma2(Wr[3], P56, A23);
        A23 = fma2(Wr[4], P67, A23);
      }
      float a0, a1, a2, a3; upk(a0, a1, A01); upk(a2, a3, A23);
      __half2 p0 = __floats2half2_rn(silu_f(a0), silu_f(a1));
      __half2 p1 = __floats2half2_rn(silu_f(a2), silu_f(a3));
      youtA[2 * ii]     = *reinterpret_cast<unsigned*>(&p0);
      youtA[2 * ii + 1] = *reinterpret_cast<unsigned*>(&p1);
    }
    __syncwarp();   // all halo reads (within this warp's 4 channels) done
    #pragma unroll
    for (int ii = 0; ii < 8; ii++) {
      int g = 8 * iA[ii] + sub;
      int h = g >> 4, wq = g & 15;
      int off = y1off(h * 32 + wq * 2);
      *reinterpret_cast<uint2*>(&sm[cc * CH_STRIDE + off]) =
          make_uint2(youtA[2 * ii], youtA[2 * ii + 1]);
    }
    // pass B: h in {2..5} read only center rows -> store immediately
    #pragma unroll
    for (int i = 4; i < 12; i++) {
      int g = 8 * i + sub;
      int h = g >> 4, wq = g & 15;
      ull A01 = pk(t1, t1), A23 = A01;
      #pragma unroll
      for (int r = 0; r < 5; r++) {
        const float* row = chan + (h + r) * 72 + wq * 4;
        float4 va = *reinterpret_cast<const float4*>(row);
        float4 vb = *reinterpret_cast<const float4*>(row + 4);
        ull P01 = pk(va.x, va.y), P12 = pk(va.y, va.z), P23 = pk(va.z, va.w),
            P34 = pk(va.w, vb.x), P45 = pk(vb.x, vb.y), P56 = pk(vb.y, vb.z),
            P67 = pk(vb.z, vb.w);
        const ull* Wr = &W2r[r * 5];
        A01 = fma2(Wr[0], P01, A01); A01 = fma2(Wr[1], P12, A01);
        A01 = fma2(Wr[2], P23, A01); A01 = fma2(Wr[3], P34, A01);
        A01 = fma2(Wr[4], P45, A01);
        A23 = fma2(Wr[0], P23, A23); A23 = fma2(Wr[1], P34, A23);
        A23 = fma2(Wr[2], P45, A23); A23 = fma2(Wr[3], P56, A23);
        A23 = fma2(Wr[4], P67, A23);
      }
      float a0, a1, a2, a3; upk(a0, a1, A01); upk(a2, a3, A23);
      __half2 p0 = __floats2half2_rn(silu_f(a0), silu_f(a1));
      __half2 p1 = __floats2half2_rn(silu_f(a2), silu_f(a3));
      int off = y1off(h * 32 + wq * 2);
      *reinterpret_cast<uint2*>(&sm[cc * CH_STRIDE + off]) =
          make_uint2(*reinterpret_cast<unsigned*>(&p0),
                     *reinterpret_cast<unsigned*>(&p1));
    }
  }
  __syncthreads();

  // ---- phase 3: pointwise branch + attn + top-38 threshold + output ----
  {
    int hl = tid >> 6, w = tid & 63;
    const float* xcol = &sm[(hl + 2) * 72 + w + 2];  // + c*CH_STRIDE
    // pass 1: h[8] = b1 + W1 x  (packed pairs)
    ull h2[4];
    h2[0] = pk(sm[B1_OFF + 0], sm[B1_OFF + 1]);
    h2[1] = pk(sm[B1_OFF + 2], sm[B1_OFF + 3]);
    h2[2] = pk(sm[B1_OFF + 4], sm[B1_OFF + 5]);
    h2[3] = pk(sm[B1_OFF + 6], sm[B1_OFF + 7]);
    #pragma unroll
    for (int c = 0; c < 64; c++) {
      float xv = xcol[c * CH_STRIDE];
      ull xx = pk(xv, xv);
      float4 wa = *reinterpret_cast<const float4*>(&sm[W1T_OFF + c * 8]);
      float4 wb = *reinterpret_cast<const float4*>(&sm[W1T_OFF + c * 8 + 4]);
      h2[0] = fma2(pk(wa.x, wa.y), xx, h2[0]);
      h2[1] = fma2(pk(wa.z, wa.w), xx, h2[1]);
      h2[2] = fma2(pk(wb.x, wb.y), xx, h2[2]);
      h2[3] = fma2(pk(wb.z, wb.w), xx, h2[3]);
    }
    ull hb2[4];
    #pragma unroll
    for (int j = 0; j < 4; j++) {
      float u, v; upk(u, v, h2[j]);
      hb2[j] = pk(silu_f(u), silu_f(v));
    }

    int yoff = y1off(hl * 32 + (w >> 1));
    int wpar = w & 1;

    // pass 2: attn values + sort for threshold
    float s[64];
    #pragma unroll
    for (int c = 0; c < 64; c++) s[c] = attn_val(sm, c, yoff, wpar, hb2);
    sort64(s);
    float thr = s[26];
    float alphav = sm[ALPHA_OFF];

    // pass 3: recompute attn (bit-identical) + write out
    size_t ob = (size_t)b * 4194304 + (size_t)d * 4096 +
                (size_t)(hs * 8 + hl) * 64 + w;
    #pragma unroll
    for (int c = 0; c < 64; c++) {
      float a  = attn_val(sm, c, yoff, wpar, hb2);
      float xv = xcol[c * CH_STRIDE];
      float r  = (a >= thr) ? fmaf(alphav, a, xv) : xv;
      out[ob + (size_t)c * 65536] = r;
    }
  }
}

extern "C" void kernel_launch(void* const* d_in, const int* in_sizes, int n_in,
                              void* d_out, int out_size) {
  const float* x    = (const float*)d_in[0];
  const float* wdw  = (const float*)d_in[1];
  const float* g1   = (const float*)d_in[2];
  const float* be1  = (const float*)d_in[3];
  const float* m1   = (const float*)d_in[4];
  const float* v1   = (const float*)d_in[5];
  const float* wp1  = (const float*)d_in[6];
  const float* bp1  = (const float*)d_in[7];
  const float* g2   = (const float*)d_in[8];
  const float* be2  = (const float*)d_in[9];
  const float* m2   = (const float*)d_in[10];
  const float* v2   = (const float*)d_in[11];
  const float* wp2  = (const float*)d_in[12];
  const float* bp2  = (const float*)d_in[13];
  const float* alpha= (const float*)d_in[14];
  float* out = (float*)d_out;

  cudaFuncSetAttribute(k_fused, cudaFuncAttributeMaxDynamicSharedMemorySize,
                       SMEM_BYTES);
  k_fused<<<512, 512, SMEM_BYTES>>>(x, out, wdw, g1, be1, m1, v1, wp1, bp1,
                                    g2, be2, m2, v2, wp2, bp2, alpha);
}